// round 6
// baseline (speedup 1.0000x reference)
#include <cuda_runtime.h>
#include <cuda_bf16.h>
#include <mma.h>
#include <math.h>
#include <cstdint>

using namespace nvcuda;

// Problem dims
static constexpr int Bn = 256, Sn = 20, En = 512, Hn = 512, Vn = 32000;
static constexpr int DIN1 = Sn * En + 2 * En;   // 11264
static constexpr int K1   = DIN1 + Hn;          // 11776 ([x | h0] concat)
static constexpr int NG   = 4 * Hn;             // 2048 gates

// Scratch (device globals; allocation is forbidden)
__device__ float g_x[Bn * K1];          // [enc_flat | we | spk_emb | h0]
__device__ float g_part[8 * Bn * NG];   // split-K partials (max KS=8)
__device__ float g_ws[3 * Hn * NG];     // W+U for layers 2-4
__device__ float g_hA[Bn * Hn], g_hB[Bn * Hn], g_h4[Bn * Hn], g_c[Bn * Hn];

// ---------------------------------------------------------------------------
// Build concatenated input row: [enc(10240) | we(512) | pe[spk](512) | h0(512)]
// ---------------------------------------------------------------------------
__global__ void build_x(const float* __restrict__ enc, const float* __restrict__ we,
                        const float* __restrict__ h0, const int* __restrict__ spk,
                        const float* __restrict__ pe) {
    int idx = blockIdx.x * blockDim.x + threadIdx.x;
    if (idx >= Bn * K1) return;
    int b = idx / K1;
    int k = idx - b * K1;
    float v;
    if (k < Sn * En)            v = enc[b * Sn * En + k];
    else if (k < Sn * En + En)  v = we[b * En + (k - Sn * En)];
    else if (k < DIN1)          v = pe[spk[b] * En + (k - Sn * En - En)];
    else                        v = h0[b * Hn + (k - DIN1)];
    g_x[idx] = v;
}

__global__ void wsum_add(const float* __restrict__ W, const float* __restrict__ U,
                         float* __restrict__ o) {
    int i = blockIdx.x * blockDim.x + threadIdx.x;
    if (i < Hn * NG) o[i] = W[i] + U[i];
}

// ---------------------------------------------------------------------------
// Split-bf16 tensor-core GEMM (3-MMA error compensation), TALL tile.
// C_partial(MxN) = A(MxK) @ B(KxN);  M == 256 covered by ONE block row so every
// B (weight) byte is streamed from DRAM exactly once.
// MODE 0: B = B0.  MODE 1: B row gk < Ksplit from B0, else B1[gk-Ksplit].
// Block tile 256x64, BK=32, 256 threads (8 warps 4x2), warp tile 64x32.
// grid = (N/64, 1, KS); output to Cout + ks*M*N.
// Loader: LDG f32 (reg double-buffered) -> split hi/lo bf16 -> STS.
// 2 SMEM stages, one __syncthreads per K-iter.
// ---------------------------------------------------------------------------
static constexpr int ALD = 40;                 // halfs per A row (32 + pad 8)
static constexpr int BLD = 72;                 // halfs per B row (64 + pad 8)
static constexpr int A_HALFS = 256 * ALD;      // 10240
static constexpr int B_HALFS = 32 * BLD;       // 2304
// layout: Ah[2] Al[2] Bh[2] Bl[2]
static constexpr int GEMM_SMEM_BYTES = (4 * A_HALFS + 4 * B_HALFS) * 2;  // 100352

__device__ __forceinline__ void split4(const float4 f, __nv_bfloat16* hi,
                                       __nv_bfloat16* lo) {
    float v[4] = {f.x, f.y, f.z, f.w};
#pragma unroll
    for (int i = 0; i < 4; i++) {
        __nv_bfloat16 h = __float2bfloat16_rn(v[i]);
        hi[i] = h;
        lo[i] = __float2bfloat16_rn(v[i] - __bfloat162float(h));
    }
}

template <int MODE>
__global__ __launch_bounds__(256)
void gemm_tall(const float* __restrict__ A, const float* __restrict__ B0,
               const float* __restrict__ B1, float* __restrict__ Cout,
               int M, int N, int K, int Ksplit, int Kchunk) {
    extern __shared__ __nv_bfloat16 sm[];
    __nv_bfloat16* Ah = sm;                    // [2][A_HALFS]
    __nv_bfloat16* Al = sm + 2 * A_HALFS;
    __nv_bfloat16* Bh = sm + 4 * A_HALFS;      // [2][B_HALFS]
    __nv_bfloat16* Bl = sm + 4 * A_HALFS + 2 * B_HALFS;

    const int n0 = blockIdx.x * 64;
    const int ks = blockIdx.z;
    const int kbase = ks * Kchunk;
    const int iters = Kchunk / 32;
    const int tid = threadIdx.x;

    // A loader: thread -> full row tid (0..255), 8 float4 (32 f32)
    // B loader: row = tid>>3 (0..31), col base (tid&7)*8, 2 float4
    const int b_row = tid >> 3;
    const int b_col = (tid & 7) * 8;

    const int wid = tid >> 5;
    const int wm = wid >> 1;   // 0..3 -> m offset wm*64
    const int wn = wid & 1;    // 0..1 -> n offset wn*32

    const float* Agp = A + (size_t)tid * K + kbase;

    wmma::fragment<wmma::accumulator, 16, 16, 16, float> acc[4][2];
#pragma unroll
    for (int i = 0; i < 4; i++)
#pragma unroll
        for (int j = 0; j < 2; j++) wmma::fill_fragment(acc[i][j], 0.f);

    float4 aReg[8];
    float4 bReg[2];

    auto ldg_stage = [&](int it) {
#pragma unroll
        for (int j = 0; j < 8; j++)
            aReg[j] = *(const float4*)(Agp + it * 32 + j * 4);
        int gk = kbase + it * 32 + b_row;
        const float* brow;
        if (MODE == 1 && gk >= Ksplit)
            brow = B1 + (size_t)(gk - Ksplit) * N + n0 + b_col;
        else
            brow = B0 + (size_t)gk * N + n0 + b_col;
#pragma unroll
        for (int j = 0; j < 2; j++) bReg[j] = *(const float4*)(brow + j * 4);
    };

    auto sts_stage = [&](int s) {
        __nv_bfloat16 h4v[4], l4v[4];
#pragma unroll
        for (int j = 0; j < 8; j++) {
            split4(aReg[j], h4v, l4v);
            int off = s * A_HALFS + tid * ALD + j * 4;
            *(uint2*)&Ah[off] = *(uint2*)h4v;
            *(uint2*)&Al[off] = *(uint2*)l4v;
        }
#pragma unroll
        for (int j = 0; j < 2; j++) {
            split4(bReg[j], h4v, l4v);
            int off = s * B_HALFS + b_row * BLD + b_col + j * 4;
            *(uint2*)&Bh[off] = *(uint2*)h4v;
            *(uint2*)&Bl[off] = *(uint2*)l4v;
        }
    };

    ldg_stage(0);

    for (int it = 0; it < iters; ++it) {
        const int s = it & 1;
        sts_stage(s);
        if (it + 1 < iters) ldg_stage(it + 1);   // LDG in flight during MMA
        __syncthreads();

        const __nv_bfloat16* ah = Ah + s * A_HALFS + (wm * 64) * ALD;
        const __nv_bfloat16* al = Al + s * A_HALFS + (wm * 64) * ALD;
        const __nv_bfloat16* bh = Bh + s * B_HALFS + wn * 32;
        const __nv_bfloat16* bl = Bl + s * B_HALFS + wn * 32;

#pragma unroll
        for (int kk = 0; kk < 2; ++kk) {
            wmma::fragment<wmma::matrix_a, 16, 16, 16, __nv_bfloat16,
                           wmma::row_major> afh[4], afl[4];
            wmma::fragment<wmma::matrix_b, 16, 16, 16, __nv_bfloat16,
                           wmma::row_major> bfh[2], bfl[2];
#pragma unroll
            for (int i = 0; i < 4; i++) {
                wmma::load_matrix_sync(afh[i], ah + i * 16 * ALD + kk * 16, ALD);
                wmma::load_matrix_sync(afl[i], al + i * 16 * ALD + kk * 16, ALD);
            }
#pragma unroll
            for (int j = 0; j < 2; j++) {
                wmma::load_matrix_sync(bfh[j], bh + kk * 16 * BLD + j * 16, BLD);
                wmma::load_matrix_sync(bfl[j], bl + kk * 16 * BLD + j * 16, BLD);
            }
#pragma unroll
            for (int i = 0; i < 4; i++)
#pragma unroll
                for (int j = 0; j < 2; j++) {
                    wmma::mma_sync(acc[i][j], afh[i], bfh[j], acc[i][j]);
                    wmma::mma_sync(acc[i][j], afh[i], bfl[j], acc[i][j]);
                    wmma::mma_sync(acc[i][j], afl[i], bfh[j], acc[i][j]);
                }
        }
        // next iter writes stage s^1; all its readers passed the barrier above
    }

    float* C = Cout + (size_t)ks * M * N;
#pragma unroll
    for (int i = 0; i < 4; i++)
#pragma unroll
        for (int j = 0; j < 2; j++)
            wmma::store_matrix_sync(
                C + (size_t)(wm * 64 + i * 16) * N + n0 + wn * 32 + j * 16,
                acc[i][j], N, wmma::mem_row_major);
}

// ---------------------------------------------------------------------------
// Gate kernel: reduce KS split-K partials + bias, apply LSTM nonlinearity
// (Keras order i,f,g,o; activation=relu).
// ---------------------------------------------------------------------------
__global__ void lstm_gate(const float* __restrict__ P, int KS,
                          const float* __restrict__ c_prev, float* __restrict__ c_out,
                          const float* __restrict__ bias, float* __restrict__ h_out) {
    int idx = blockIdx.x * blockDim.x + threadIdx.x;
    if (idx >= Bn * Hn) return;
    int b = idx / Hn;
    int j = idx - b * Hn;
    float zi = bias[j], zf = bias[Hn + j], zg = bias[2 * Hn + j], zo = bias[3 * Hn + j];
    for (int ks = 0; ks < KS; ks++) {
        const float* zr = P + ((size_t)ks * Bn + b) * NG;
        zi += zr[j]; zf += zr[Hn + j]; zg += zr[2 * Hn + j]; zo += zr[3 * Hn + j];
    }
    float ig = 1.f / (1.f + expf(-zi));
    float fg = 1.f / (1.f + expf(-zf));
    float gg = fmaxf(zg, 0.f);
    float og = 1.f / (1.f + expf(-zo));
    float cn = fg * c_prev[idx] + ig * gg;
    c_out[idx] = cn;
    h_out[idx] = og * fmaxf(cn, 0.f);
}

// ---------------------------------------------------------------------------
// Softmax in place on (Bn x Vn), one block per row; adds bias bd to the logits.
// ---------------------------------------------------------------------------
__global__ __launch_bounds__(512)
void softmax_bias(float* __restrict__ probs, const float* __restrict__ bd) {
    const int b = blockIdx.x;
    float* row = probs + (size_t)b * Vn;
    const int tid = threadIdx.x;
    const int nt = blockDim.x;
    __shared__ float sred[33];

    float m = -3.4e38f;
    for (int i = tid; i < Vn; i += nt) m = fmaxf(m, row[i] + bd[i]);
#pragma unroll
    for (int o = 16; o > 0; o >>= 1) m = fmaxf(m, __shfl_xor_sync(0xffffffffu, m, o));
    if ((tid & 31) == 0) sred[tid >> 5] = m;
    __syncthreads();
    if (tid == 0) {
        float v = sred[0];
        for (int w = 1; w < nt / 32; w++) v = fmaxf(v, sred[w]);
        sred[32] = v;
    }
    __syncthreads();
    m = sred[32];

    float s = 0.f;
    for (int i = tid; i < Vn; i += nt) {
        float e = expf(row[i] + bd[i] - m);
        row[i] = e;
        s += e;
    }
    __syncthreads();
#pragma unroll
    for (int o = 16; o > 0; o >>= 1) s += __shfl_xor_sync(0xffffffffu, s, o);
    if ((tid & 31) == 0) sred[tid >> 5] = s;
    __syncthreads();
    if (tid == 0) {
        float v = 0.f;
        for (int w = 0; w < nt / 32; w++) v += sred[w];
        sred[32] = v;
    }
    __syncthreads();
    float inv = 1.f / sred[32];
    for (int i = tid; i < Vn; i += nt) row[i] *= inv;
}

__global__ void copy_tail(const float* __restrict__ h4, const float* __restrict__ c4,
                          float* __restrict__ out) {
    int i = blockIdx.x * blockDim.x + threadIdx.x;
    if (i >= Bn * Hn) return;
    out[(size_t)Bn * Vn + i] = h4[i];
    out[(size_t)Bn * Vn + (size_t)Bn * Hn + i] = c4[i];
}

// ---------------------------------------------------------------------------
// Launch
// ---------------------------------------------------------------------------
extern "C" void kernel_launch(void* const* d_in, const int* in_sizes, int n_in,
                              void* d_out, int out_size) {
    const float* enc = (const float*)d_in[0];
    const float* we  = (const float*)d_in[1];
    const float* h0  = (const float*)d_in[2];
    const float* c0  = (const float*)d_in[3];
    const int*   spk = (const int*)d_in[4];
    // d_in[5] = addressee (unused)
    const float* pe  = (const float*)d_in[6];
    const float* W1 = (const float*)d_in[7];
    const float* U1 = (const float*)d_in[8];
    const float* b1 = (const float*)d_in[9];
    const float* W2 = (const float*)d_in[10];
    const float* U2 = (const float*)d_in[11];
    const float* b2 = (const float*)d_in[12];
    const float* W3 = (const float*)d_in[13];
    const float* U3 = (const float*)d_in[14];
    const float* b3 = (const float*)d_in[15];
    const float* W4 = (const float*)d_in[16];
    const float* U4 = (const float*)d_in[17];
    const float* b4 = (const float*)d_in[18];
    const float* Wd = (const float*)d_in[19];
    const float* bd = (const float*)d_in[20];
    float* out = (float*)d_out;

    float *xp, *pp, *ws, *hA, *hB, *h4, *cp;
    cudaGetSymbolAddress((void**)&xp, g_x);
    cudaGetSymbolAddress((void**)&pp, g_part);
    cudaGetSymbolAddress((void**)&ws, g_ws);
    cudaGetSymbolAddress((void**)&hA, g_hA);
    cudaGetSymbolAddress((void**)&hB, g_hB);
    cudaGetSymbolAddress((void**)&h4, g_h4);
    cudaGetSymbolAddress((void**)&cp, g_c);

    cudaFuncSetAttribute(gemm_tall<0>, cudaFuncAttributeMaxDynamicSharedMemorySize,
                         GEMM_SMEM_BYTES);
    cudaFuncSetAttribute(gemm_tall<1>, cudaFuncAttributeMaxDynamicSharedMemorySize,
                         GEMM_SMEM_BYTES);

    // Prep: concat input + per-layer W+U sums (x==h makes the fold exact)
    build_x<<<(Bn * K1 + 255) / 256, 256>>>(enc, we, h0, spk, pe);
    wsum_add<<<(Hn * NG + 255) / 256, 256>>>(W2, U2, ws);
    wsum_add<<<(Hn * NG + 255) / 256, 256>>>(W3, U3, ws + Hn * NG);
    wsum_add<<<(Hn * NG + 255) / 256, 256>>>(W4, U4, ws + 2 * Hn * NG);

    // Layer 1: z = [x|h0] @ [W1;U1]  (K=11776, split 11264, KS=8, Kchunk=1472)
    gemm_tall<1><<<dim3(NG / 64, 1, 8), 256, GEMM_SMEM_BYTES>>>(
        xp, W1, U1, pp, Bn, NG, K1, DIN1, K1 / 8);
    lstm_gate<<<(Bn * Hn + 255) / 256, 256>>>(pp, 8, c0, cp, b1, hA);

    // Layers 2-4: z = h @ (W+U)  (K=512, KS=4, Kchunk=128)
    gemm_tall<0><<<dim3(NG / 64, 1, 4), 256, GEMM_SMEM_BYTES>>>(
        hA, ws, nullptr, pp, Bn, NG, Hn, 0, Hn / 4);
    lstm_gate<<<(Bn * Hn + 255) / 256, 256>>>(pp, 4, cp, cp, b2, hB);

    gemm_tall<0><<<dim3(NG / 64, 1, 4), 256, GEMM_SMEM_BYTES>>>(
        hB, ws + Hn * NG, nullptr, pp, Bn, NG, Hn, 0, Hn / 4);
    lstm_gate<<<(Bn * Hn + 255) / 256, 256>>>(pp, 4, cp, cp, b3, hA);

    gemm_tall<0><<<dim3(NG / 64, 1, 4), 256, GEMM_SMEM_BYTES>>>(
        hA, ws + 2 * Hn * NG, nullptr, pp, Bn, NG, Hn, 0, Hn / 4);
    lstm_gate<<<(Bn * Hn + 255) / 256, 256>>>(pp, 4, cp, cp, b4, h4);

    // Decode: logits = h4 @ Wd (KS=1, direct into out; bias folded in softmax)
    gemm_tall<0><<<dim3(Vn / 64, 1, 1), 256, GEMM_SMEM_BYTES>>>(
        h4, Wd, nullptr, out, Bn, Vn, Hn, 0, Hn);
    softmax_bias<<<Bn, 512>>>(out, bd);

    if (out_size >= Bn * Vn + 2 * Bn * Hn) {
        copy_tail<<<(Bn * Hn + 255) / 256, 256>>>(h4, cp, out);
    }
}

// round 7
// speedup vs baseline: 1.7541x; 1.7541x over previous
#include <cuda_runtime.h>
#include <cuda_fp16.h>
#include <mma.h>
#include <math.h>
#include <cstdint>

using namespace nvcuda;

// Problem dims
static constexpr int Bn = 256, Sn = 20, En = 512, Hn = 512, Vn = 32000;
static constexpr int DIN1 = Sn * En + 2 * En;   // 11264
static constexpr int K1   = DIN1 + Hn;          // 11776 ([x | h0] concat)
static constexpr int NG   = 4 * Hn;             // 2048 gates

// Scratch (device globals; allocation is forbidden)
__device__ float g_x[Bn * K1];          // [enc_flat | we | spk_emb | h0]
__device__ float g_part[8 * Bn * NG];   // split-K partials (max KS=8)
__device__ float g_hdup[Bn * 2 * Hn];   // [h | h] for layers 2-4
__device__ float g_h4[Bn * Hn];
__device__ float g_c[Bn * Hn];

// ---------------------------------------------------------------------------
// Build concatenated input row: [enc(10240) | we(512) | pe[spk](512) | h0(512)]
// ---------------------------------------------------------------------------
__global__ void build_x(const float* __restrict__ enc, const float* __restrict__ we,
                        const float* __restrict__ h0, const int* __restrict__ spk,
                        const float* __restrict__ pe) {
    int idx = blockIdx.x * blockDim.x + threadIdx.x;
    if (idx >= Bn * K1) return;
    int b = idx / K1;
    int k = idx - b * K1;
    float v;
    if (k < Sn * En)            v = enc[b * Sn * En + k];
    else if (k < Sn * En + En)  v = we[b * En + (k - Sn * En)];
    else if (k < DIN1)          v = pe[spk[b] * En + (k - Sn * En - En)];
    else                        v = h0[b * Hn + (k - DIN1)];
    g_x[idx] = v;
}

// ---------------------------------------------------------------------------
// fp16 tensor-core GEMM with 2-MMA B-split error compensation.
//   A -> fp16 (single rounding, rel err ~2^-12 on activations)
//   B -> bh + bl (fp16 pair, weights represented to ~2^-22)
//   acc += a*bh; acc += a*bl   (fp32 accumulator)
// C_partial(MxN) = A(MxK) @ B(KxN).
// MODE 0: B = B0.  MODE 1: B row gk < Ksplit from B0, else B1[gk-Ksplit].
// Block tile 128x64, BK=32, 256 threads (8 warps 4x2), warp tile 32x32.
// grid = (N/64, M/128, KS); output to Cout + ks*M*N.
// Loader: LDG f32 (reg double-buffered) -> convert/split -> STS.
// Static SMEM (38.9KB): A[2] plane + Bh[2] + Bl[2]; one barrier per K-iter.
// ---------------------------------------------------------------------------
static constexpr int ALD = 40;                 // halfs per A row (32 + pad 8)
static constexpr int BLD = 72;                 // halfs per B row (64 + pad 8)
static constexpr int A_HALFS = 128 * ALD;      // 5120
static constexpr int B_HALFS = 32 * BLD;       // 2304

__device__ __forceinline__ void cvt4(const float4 f, __half* o) {
    o[0] = __float2half_rn(f.x);
    o[1] = __float2half_rn(f.y);
    o[2] = __float2half_rn(f.z);
    o[3] = __float2half_rn(f.w);
}
__device__ __forceinline__ void split4h(const float4 f, __half* hi, __half* lo) {
    float v[4] = {f.x, f.y, f.z, f.w};
#pragma unroll
    for (int i = 0; i < 4; i++) {
        __half h = __float2half_rn(v[i]);
        hi[i] = h;
        lo[i] = __float2half_rn(v[i] - __half2float(h));
    }
}

template <int MODE>
__global__ __launch_bounds__(256, 2)
void gemm_fp16s(const float* __restrict__ A, const float* __restrict__ B0,
                const float* __restrict__ B1, float* __restrict__ Cout,
                int M, int N, int K, int Ksplit, int Kchunk) {
    __shared__ __half Ah[2][A_HALFS];
    __shared__ __half Bh[2][B_HALFS];
    __shared__ __half Bl[2][B_HALFS];

    const int n0 = blockIdx.x * 64;
    const int m0 = blockIdx.y * 128;
    const int ks = blockIdx.z;
    const int kbase = ks * Kchunk;
    const int iters = Kchunk / 32;
    const int tid = threadIdx.x;

    // A loader: row = tid>>1 (0..127), col base (tid&1)*16, 4 float4
    const int a_row = tid >> 1;
    const int a_col = (tid & 1) * 16;
    // B loader: row = tid>>3 (0..31), col base (tid&7)*8, 2 float4
    const int b_row = tid >> 3;
    const int b_col = (tid & 7) * 8;

    const int wid = tid >> 5;
    const int wm = wid >> 1;   // 0..3 -> m offset wm*32
    const int wn = wid & 1;    // 0..1 -> n offset wn*32

    const float* Agp = A + (size_t)(m0 + a_row) * K + a_col + kbase;

    wmma::fragment<wmma::accumulator, 16, 16, 16, float> acc[2][2];
#pragma unroll
    for (int i = 0; i < 2; i++)
#pragma unroll
        for (int j = 0; j < 2; j++) wmma::fill_fragment(acc[i][j], 0.f);

    float4 aReg[4];
    float4 bReg[2];

    auto ldg_stage = [&](int it) {
#pragma unroll
        for (int j = 0; j < 4; j++)
            aReg[j] = *(const float4*)(Agp + it * 32 + j * 4);
        int gk = kbase + it * 32 + b_row;
        const float* brow;
        if (MODE == 1 && gk >= Ksplit)
            brow = B1 + (size_t)(gk - Ksplit) * N + n0 + b_col;
        else
            brow = B0 + (size_t)gk * N + n0 + b_col;
#pragma unroll
        for (int j = 0; j < 2; j++) bReg[j] = *(const float4*)(brow + j * 4);
    };

    auto sts_stage = [&](int s) {
        __half q[4], hq[4], lq[4];
#pragma unroll
        for (int j = 0; j < 4; j++) {
            cvt4(aReg[j], q);
            *(uint2*)&Ah[s][a_row * ALD + a_col + j * 4] = *(uint2*)q;
        }
#pragma unroll
        for (int j = 0; j < 2; j++) {
            split4h(bReg[j], hq, lq);
            int off = b_row * BLD + b_col + j * 4;
            *(uint2*)&Bh[s][off] = *(uint2*)hq;
            *(uint2*)&Bl[s][off] = *(uint2*)lq;
        }
    };

    ldg_stage(0);

    for (int it = 0; it < iters; ++it) {
        const int s = it & 1;
        sts_stage(s);
        if (it + 1 < iters) ldg_stage(it + 1);   // LDG in flight during MMA
        __syncthreads();

        const __half* ah = &Ah[s][(wm * 32) * ALD];
        const __half* bh = &Bh[s][wn * 32];
        const __half* bl = &Bl[s][wn * 32];

#pragma unroll
        for (int kk = 0; kk < 2; ++kk) {
            wmma::fragment<wmma::matrix_a, 16, 16, 16, __half, wmma::row_major> af[2];
            wmma::fragment<wmma::matrix_b, 16, 16, 16, __half, wmma::row_major> bfh[2],
                bfl[2];
#pragma unroll
            for (int i = 0; i < 2; i++)
                wmma::load_matrix_sync(af[i], ah + i * 16 * ALD + kk * 16, ALD);
#pragma unroll
            for (int j = 0; j < 2; j++) {
                wmma::load_matrix_sync(bfh[j], bh + kk * 16 * BLD + j * 16, BLD);
                wmma::load_matrix_sync(bfl[j], bl + kk * 16 * BLD + j * 16, BLD);
            }
#pragma unroll
            for (int i = 0; i < 2; i++)
#pragma unroll
                for (int j = 0; j < 2; j++) {
                    wmma::mma_sync(acc[i][j], af[i], bfh[j], acc[i][j]);
                    wmma::mma_sync(acc[i][j], af[i], bfl[j], acc[i][j]);
                }
        }
        // next iter writes stage s^1; all its readers passed the barrier above
    }

    float* C = Cout + (size_t)ks * M * N;
#pragma unroll
    for (int i = 0; i < 2; i++)
#pragma unroll
        for (int j = 0; j < 2; j++)
            wmma::store_matrix_sync(
                C + (size_t)(m0 + wm * 32 + i * 16) * N + n0 + wn * 32 + j * 16,
                acc[i][j], N, wmma::mem_row_major);
}

// ---------------------------------------------------------------------------
// Gate kernel: reduce KS split-K partials + bias, apply LSTM nonlinearity
// (Keras order i,f,g,o; activation=relu). Writes duplicated [h|h] and/or flat h.
// ---------------------------------------------------------------------------
__global__ void lstm_gate(const float* __restrict__ P, int KS,
                          const float* __restrict__ c_prev, float* __restrict__ c_out,
                          const float* __restrict__ bias,
                          float* __restrict__ hdup, float* __restrict__ hflat) {
    int idx = blockIdx.x * blockDim.x + threadIdx.x;
    if (idx >= Bn * Hn) return;
    int b = idx / Hn;
    int j = idx - b * Hn;
    float zi = bias[j], zf = bias[Hn + j], zg = bias[2 * Hn + j], zo = bias[3 * Hn + j];
    for (int ks = 0; ks < KS; ks++) {
        const float* zr = P + ((size_t)ks * Bn + b) * NG;
        zi += zr[j]; zf += zr[Hn + j]; zg += zr[2 * Hn + j]; zo += zr[3 * Hn + j];
    }
    float ig = 1.f / (1.f + expf(-zi));
    float fg = 1.f / (1.f + expf(-zf));
    float gg = fmaxf(zg, 0.f);
    float og = 1.f / (1.f + expf(-zo));
    float cn = fg * c_prev[idx] + ig * gg;
    c_out[idx] = cn;
    float h = og * fmaxf(cn, 0.f);
    if (hdup) {
        hdup[(size_t)b * 2 * Hn + j] = h;
        hdup[(size_t)b * 2 * Hn + Hn + j] = h;
    }
    if (hflat) hflat[idx] = h;
}

// ---------------------------------------------------------------------------
// SMEM-staged softmax on (Bn x Vn): one global read + one global write.
// Adds bias bd to the logits. Dynamic smem = Vn floats (125KB).
// ---------------------------------------------------------------------------
__global__ __launch_bounds__(512)
void softmax_smem(float* __restrict__ probs, const float* __restrict__ bd) {
    extern __shared__ float sx[];
    const int b = blockIdx.x;
    float* row = probs + (size_t)b * Vn;
    const int tid = threadIdx.x;
    const int nt = 512;
    __shared__ float sred[33];

    // pass 1: load + bias into smem, tracking max
    float m = -3.4e38f;
    for (int i = tid; i < Vn; i += nt) {
        float v = row[i] + bd[i];
        sx[i] = v;
        m = fmaxf(m, v);
    }
#pragma unroll
    for (int o = 16; o > 0; o >>= 1) m = fmaxf(m, __shfl_xor_sync(0xffffffffu, m, o));
    if ((tid & 31) == 0) sred[tid >> 5] = m;
    __syncthreads();
    if (tid == 0) {
        float v = sred[0];
        for (int w = 1; w < nt / 32; w++) v = fmaxf(v, sred[w]);
        sred[32] = v;
    }
    __syncthreads();
    m = sred[32];

    // pass 2: exp in smem + sum
    float s = 0.f;
    for (int i = tid; i < Vn; i += nt) {
        float e = expf(sx[i] - m);
        sx[i] = e;
        s += e;
    }
    __syncthreads();   // everyone done with sred[32]
#pragma unroll
    for (int o = 16; o > 0; o >>= 1) s += __shfl_xor_sync(0xffffffffu, s, o);
    if ((tid & 31) == 0) sred[tid >> 5] = s;
    __syncthreads();
    if (tid == 0) {
        float v = 0.f;
        for (int w = 0; w < nt / 32; w++) v += sred[w];
        sred[32] = v;
    }
    __syncthreads();
    float inv = 1.f / sred[32];

    // pass 3: normalized write-out
    for (int i = tid; i < Vn; i += nt) row[i] = sx[i] * inv;
}

__global__ void copy_tail(const float* __restrict__ h4, const float* __restrict__ c4,
                          float* __restrict__ out) {
    int i = blockIdx.x * blockDim.x + threadIdx.x;
    if (i >= Bn * Hn) return;
    out[(size_t)Bn * Vn + i] = h4[i];
    out[(size_t)Bn * Vn + (size_t)Bn * Hn + i] = c4[i];
}

// ---------------------------------------------------------------------------
// Launch
// ---------------------------------------------------------------------------
extern "C" void kernel_launch(void* const* d_in, const int* in_sizes, int n_in,
                              void* d_out, int out_size) {
    const float* enc = (const float*)d_in[0];
    const float* we  = (const float*)d_in[1];
    const float* h0  = (const float*)d_in[2];
    const float* c0  = (const float*)d_in[3];
    const int*   spk = (const int*)d_in[4];
    // d_in[5] = addressee (unused)
    const float* pe  = (const float*)d_in[6];
    const float* W1 = (const float*)d_in[7];
    const float* U1 = (const float*)d_in[8];
    const float* b1 = (const float*)d_in[9];
    const float* W2 = (const float*)d_in[10];
    const float* U2 = (const float*)d_in[11];
    const float* b2 = (const float*)d_in[12];
    const float* W3 = (const float*)d_in[13];
    const float* U3 = (const float*)d_in[14];
    const float* b3 = (const float*)d_in[15];
    const float* W4 = (const float*)d_in[16];
    const float* U4 = (const float*)d_in[17];
    const float* b4 = (const float*)d_in[18];
    const float* Wd = (const float*)d_in[19];
    const float* bd = (const float*)d_in[20];
    float* out = (float*)d_out;

    float *xp, *pp, *hd, *h4, *cp;
    cudaGetSymbolAddress((void**)&xp, g_x);
    cudaGetSymbolAddress((void**)&pp, g_part);
    cudaGetSymbolAddress((void**)&hd, g_hdup);
    cudaGetSymbolAddress((void**)&h4, g_h4);
    cudaGetSymbolAddress((void**)&cp, g_c);

    cudaFuncSetAttribute(softmax_smem, cudaFuncAttributeMaxDynamicSharedMemorySize,
                         Vn * (int)sizeof(float));

    // 1. Build concatenated input
    build_x<<<(Bn * K1 + 255) / 256, 256>>>(enc, we, h0, spk, pe);

    // 2. Layer 1: z = [x|h0] @ [W1;U1]  (K=11776, split 11264, KS=8)
    gemm_fp16s<1><<<dim3(NG / 64, Bn / 128, 8), 256>>>(
        xp, W1, U1, pp, Bn, NG, K1, DIN1, K1 / 8);
    lstm_gate<<<(Bn * Hn + 255) / 256, 256>>>(pp, 8, c0, cp, b1, hd, nullptr);

    // 3. Layers 2-4: z = [h|h] @ [W;U]  (K=1024, split 512, KS=4)
    gemm_fp16s<1><<<dim3(NG / 64, Bn / 128, 4), 256>>>(
        hd, W2, U2, pp, Bn, NG, 2 * Hn, Hn, 2 * Hn / 4);
    lstm_gate<<<(Bn * Hn + 255) / 256, 256>>>(pp, 4, cp, cp, b2, hd, nullptr);

    gemm_fp16s<1><<<dim3(NG / 64, Bn / 128, 4), 256>>>(
        hd, W3, U3, pp, Bn, NG, 2 * Hn, Hn, 2 * Hn / 4);
    lstm_gate<<<(Bn * Hn + 255) / 256, 256>>>(pp, 4, cp, cp, b3, hd, nullptr);

    gemm_fp16s<1><<<dim3(NG / 64, Bn / 128, 4), 256>>>(
        hd, W4, U4, pp, Bn, NG, 2 * Hn, Hn, 2 * Hn / 4);
    lstm_gate<<<(Bn * Hn + 255) / 256, 256>>>(pp, 4, cp, cp, b4, nullptr, h4);

    // 4. Decode: logits = h4 @ Wd (bias folded into softmax), softmax in place
    gemm_fp16s<0><<<dim3(Vn / 64, Bn / 128, 1), 256>>>(
        h4, Wd, nullptr, out, Bn, Vn, Hn, 0, Hn);
    softmax_smem<<<Bn, 512, Vn * sizeof(float)>>>(out, bd);

    // 5. Append h4, c4
    if (out_size >= Bn * Vn + 2 * Bn * Hn) {
        copy_tail<<<(Bn * Hn + 255) / 256, 256>>>(h4, cp, out);
    }
}

// round 8
// speedup vs baseline: 2.1269x; 1.2126x over previous
#include <cuda_runtime.h>
#include <cuda_fp16.h>
#include <mma.h>
#include <math.h>
#include <cstdint>

using namespace nvcuda;

// Problem dims
static constexpr int Bn = 256, Sn = 20, En = 512, Hn = 512, Vn = 32000;
static constexpr int DIN1 = Sn * En + 2 * En;   // 11264
static constexpr int K1   = DIN1 + Hn;          // 11776 ([x | h0] concat)
static constexpr int NG   = 4 * Hn;             // 2048 gates

// Scratch (device globals; allocation is forbidden)
__device__ float g_x[Bn * K1];          // [enc_flat | we | spk_emb | h0]
__device__ float g_part[8 * Bn * NG];   // split-K partials (max KS=8)
__device__ float g_hdup[Bn * 2 * Hn];   // [h | h] for layers 2-4
__device__ float g_h4[Bn * Hn];
__device__ float g_c[Bn * Hn];

// ---------------------------------------------------------------------------
// Build concatenated input row: [enc(10240) | we(512) | pe[spk](512) | h0(512)]
// ---------------------------------------------------------------------------
__global__ void build_x(const float* __restrict__ enc, const float* __restrict__ we,
                        const float* __restrict__ h0, const int* __restrict__ spk,
                        const float* __restrict__ pe) {
    int idx = blockIdx.x * blockDim.x + threadIdx.x;
    if (idx >= Bn * K1) return;
    int b = idx / K1;
    int k = idx - b * K1;
    float v;
    if (k < Sn * En)            v = enc[b * Sn * En + k];
    else if (k < Sn * En + En)  v = we[b * En + (k - Sn * En)];
    else if (k < DIN1)          v = pe[spk[b] * En + (k - Sn * En - En)];
    else                        v = h0[b * Hn + (k - DIN1)];
    g_x[idx] = v;
}

// ---------------------------------------------------------------------------
// Shared helpers: fp16 2-MMA B-split (A fp16 single-rounded, B = bh + bl)
// ---------------------------------------------------------------------------
static constexpr int ALD = 40;                 // halfs per A row (32 + pad 8)
static constexpr int BLD = 72;                 // halfs per B row (64 + pad 8)
static constexpr int B_HALFS = 32 * BLD;       // 2304

__device__ __forceinline__ void cvt4(const float4 f, __half* o) {
    o[0] = __float2half_rn(f.x);
    o[1] = __float2half_rn(f.y);
    o[2] = __float2half_rn(f.z);
    o[3] = __float2half_rn(f.w);
}
__device__ __forceinline__ void split4h(const float4 f, __half* hi, __half* lo) {
    float v[4] = {f.x, f.y, f.z, f.w};
#pragma unroll
    for (int i = 0; i < 4; i++) {
        __half h = __float2half_rn(v[i]);
        hi[i] = h;
        lo[i] = __float2half_rn(v[i] - __half2float(h));
    }
}

// ---------------------------------------------------------------------------
// WIDE kernel (proven R7): block 128x64, 8 warps (4x2), warp 32x32.
// Used for the small recurrent-layer GEMMs. Static smem 38.9KB, 2 CTA/SM.
// ---------------------------------------------------------------------------
static constexpr int A_HALFS_W = 128 * ALD;    // 5120

template <int MODE>
__global__ __launch_bounds__(256, 2)
void gemm_fp16s(const float* __restrict__ A, const float* __restrict__ B0,
                const float* __restrict__ B1, float* __restrict__ Cout,
                int M, int N, int K, int Ksplit, int Kchunk) {
    __shared__ __half Ah[2][A_HALFS_W];
    __shared__ __half Bh[2][B_HALFS];
    __shared__ __half Bl[2][B_HALFS];

    const int n0 = blockIdx.x * 64;
    const int m0 = blockIdx.y * 128;
    const int ks = blockIdx.z;
    const int kbase = ks * Kchunk;
    const int iters = Kchunk / 32;
    const int tid = threadIdx.x;

    const int a_row = tid >> 1;
    const int a_col = (tid & 1) * 16;
    const int b_row = tid >> 3;
    const int b_col = (tid & 7) * 8;

    const int wid = tid >> 5;
    const int wm = wid >> 1;
    const int wn = wid & 1;

    const float* Agp = A + (size_t)(m0 + a_row) * K + a_col + kbase;

    wmma::fragment<wmma::accumulator, 16, 16, 16, float> acc[2][2];
#pragma unroll
    for (int i = 0; i < 2; i++)
#pragma unroll
        for (int j = 0; j < 2; j++) wmma::fill_fragment(acc[i][j], 0.f);

    float4 aReg[4];
    float4 bReg[2];

    auto ldg_stage = [&](int it) {
#pragma unroll
        for (int j = 0; j < 4; j++)
            aReg[j] = *(const float4*)(Agp + it * 32 + j * 4);
        int gk = kbase + it * 32 + b_row;
        const float* brow;
        if (MODE == 1 && gk >= Ksplit)
            brow = B1 + (size_t)(gk - Ksplit) * N + n0 + b_col;
        else
            brow = B0 + (size_t)gk * N + n0 + b_col;
#pragma unroll
        for (int j = 0; j < 2; j++) bReg[j] = *(const float4*)(brow + j * 4);
    };

    auto sts_stage = [&](int s) {
        __half q[4], hq[4], lq[4];
#pragma unroll
        for (int j = 0; j < 4; j++) {
            cvt4(aReg[j], q);
            *(uint2*)&Ah[s][a_row * ALD + a_col + j * 4] = *(uint2*)q;
        }
#pragma unroll
        for (int j = 0; j < 2; j++) {
            split4h(bReg[j], hq, lq);
            int off = b_row * BLD + b_col + j * 4;
            *(uint2*)&Bh[s][off] = *(uint2*)hq;
            *(uint2*)&Bl[s][off] = *(uint2*)lq;
        }
    };

    ldg_stage(0);

    for (int it = 0; it < iters; ++it) {
        const int s = it & 1;
        sts_stage(s);
        if (it + 1 < iters) ldg_stage(it + 1);
        __syncthreads();

        const __half* ah = &Ah[s][(wm * 32) * ALD];
        const __half* bh = &Bh[s][wn * 32];
        const __half* bl = &Bl[s][wn * 32];

#pragma unroll
        for (int kk = 0; kk < 2; ++kk) {
            wmma::fragment<wmma::matrix_a, 16, 16, 16, __half, wmma::row_major> af[2];
            wmma::fragment<wmma::matrix_b, 16, 16, 16, __half, wmma::row_major> bfh[2],
                bfl[2];
#pragma unroll
            for (int i = 0; i < 2; i++)
                wmma::load_matrix_sync(af[i], ah + i * 16 * ALD + kk * 16, ALD);
#pragma unroll
            for (int j = 0; j < 2; j++) {
                wmma::load_matrix_sync(bfh[j], bh + kk * 16 * BLD + j * 16, BLD);
                wmma::load_matrix_sync(bfl[j], bl + kk * 16 * BLD + j * 16, BLD);
            }
#pragma unroll
            for (int i = 0; i < 2; i++)
#pragma unroll
                for (int j = 0; j < 2; j++) {
                    wmma::mma_sync(acc[i][j], af[i], bfh[j], acc[i][j]);
                    wmma::mma_sync(acc[i][j], af[i], bfl[j], acc[i][j]);
                }
        }
    }

    float* C = Cout + (size_t)ks * M * N;
#pragma unroll
    for (int i = 0; i < 2; i++)
#pragma unroll
        for (int j = 0; j < 2; j++)
            wmma::store_matrix_sync(
                C + (size_t)(m0 + wm * 32 + i * 16) * N + n0 + wn * 32 + j * 16,
                acc[i][j], N, wmma::mem_row_major);
}

// ---------------------------------------------------------------------------
// TALL kernel: block 256x64 (M=256 in ONE block), 8 warps (4x2), warp 64x32.
// 33% fewer LDSM bytes/MAC; weights stream from DRAM exactly once.
// A loader: 8 threads per row (coalesced 128B groups), 8 row-passes.
// Dynamic smem 59392B. Requires M == 256.
// ---------------------------------------------------------------------------
static constexpr int A_HALFS_T = 256 * ALD;    // 10240
static constexpr int TALL_SMEM = (2 * A_HALFS_T + 4 * B_HALFS) * 2;  // 59392

template <int MODE>
__global__ __launch_bounds__(256)
void gemm_tall16(const float* __restrict__ A, const float* __restrict__ B0,
                 const float* __restrict__ B1, float* __restrict__ Cout,
                 int N, int K, int Ksplit, int Kchunk) {
    extern __shared__ __half sm[];
    __half* Ah = sm;                            // [2][A_HALFS_T]
    __half* Bh = sm + 2 * A_HALFS_T;            // [2][B_HALFS]
    __half* Bl = sm + 2 * A_HALFS_T + 2 * B_HALFS;

    const int n0 = blockIdx.x * 64;
    const int ks = blockIdx.z;
    const int kbase = ks * Kchunk;
    const int iters = Kchunk / 32;
    const int tid = threadIdx.x;

    // A loader: rows (tid>>3) + 32p (p<8), col (tid&7)*4 — coalesced
    const int a_row = tid >> 3;
    const int a_col = (tid & 7) * 4;
    // B loader: row tid>>3 (0..31), col (tid&7)*8
    const int b_row = tid >> 3;
    const int b_col = (tid & 7) * 8;

    const int wid = tid >> 5;
    const int wm = wid >> 1;   // 0..3 -> m offset wm*64
    const int wn = wid & 1;    // 0..1 -> n offset wn*32

    const float* Agp = A + (size_t)a_row * K + kbase + a_col;

    wmma::fragment<wmma::accumulator, 16, 16, 16, float> acc[4][2];
#pragma unroll
    for (int i = 0; i < 4; i++)
#pragma unroll
        for (int j = 0; j < 2; j++) wmma::fill_fragment(acc[i][j], 0.f);

    float4 aReg[8];
    float4 bReg[2];

    auto ldg_stage = [&](int it) {
#pragma unroll
        for (int p = 0; p < 8; p++)
            aReg[p] = *(const float4*)(Agp + (size_t)(32 * p) * K + it * 32);
        int gk = kbase + it * 32 + b_row;
        const float* brow;
        if (MODE == 1 && gk >= Ksplit)
            brow = B1 + (size_t)(gk - Ksplit) * N + n0 + b_col;
        else
            brow = B0 + (size_t)gk * N + n0 + b_col;
#pragma unroll
        for (int j = 0; j < 2; j++) bReg[j] = *(const float4*)(brow + j * 4);
    };

    auto sts_stage = [&](int s) {
        __half q[4], hq[4], lq[4];
#pragma unroll
        for (int p = 0; p < 8; p++) {
            cvt4(aReg[p], q);
            *(uint2*)&Ah[s * A_HALFS_T + (a_row + 32 * p) * ALD + a_col] = *(uint2*)q;
        }
#pragma unroll
        for (int j = 0; j < 2; j++) {
            split4h(bReg[j], hq, lq);
            int off = s * B_HALFS + b_row * BLD + b_col + j * 4;
            *(uint2*)&Bh[off] = *(uint2*)hq;
            *(uint2*)&Bl[off] = *(uint2*)lq;
        }
    };

    ldg_stage(0);

    for (int it = 0; it < iters; ++it) {
        const int s = it & 1;
        sts_stage(s);
        if (it + 1 < iters) ldg_stage(it + 1);   // LDG in flight during MMA
        __syncthreads();

        const __half* ah = &Ah[s * A_HALFS_T + (wm * 64) * ALD];
        const __half* bh = &Bh[s * B_HALFS + wn * 32];
        const __half* bl = &Bl[s * B_HALFS + wn * 32];

#pragma unroll
        for (int kk = 0; kk < 2; ++kk) {
            wmma::fragment<wmma::matrix_a, 16, 16, 16, __half, wmma::row_major> af[4];
            wmma::fragment<wmma::matrix_b, 16, 16, 16, __half, wmma::row_major> bfh[2],
                bfl[2];
#pragma unroll
            for (int i = 0; i < 4; i++)
                wmma::load_matrix_sync(af[i], ah + i * 16 * ALD + kk * 16, ALD);
#pragma unroll
            for (int j = 0; j < 2; j++) {
                wmma::load_matrix_sync(bfh[j], bh + kk * 16 * BLD + j * 16, BLD);
                wmma::load_matrix_sync(bfl[j], bl + kk * 16 * BLD + j * 16, BLD);
            }
#pragma unroll
            for (int i = 0; i < 4; i++)
#pragma unroll
                for (int j = 0; j < 2; j++) {
                    wmma::mma_sync(acc[i][j], af[i], bfh[j], acc[i][j]);
                    wmma::mma_sync(acc[i][j], af[i], bfl[j], acc[i][j]);
                }
        }
    }

    float* C = Cout + (size_t)ks * 256 * N;
#pragma unroll
    for (int i = 0; i < 4; i++)
#pragma unroll
        for (int j = 0; j < 2; j++)
            wmma::store_matrix_sync(
                C + (size_t)(wm * 64 + i * 16) * N + n0 + wn * 32 + j * 16,
                acc[i][j], N, wmma::mem_row_major);
}

// ---------------------------------------------------------------------------
// Gate kernel: reduce KS split-K partials + bias, apply LSTM nonlinearity
// (Keras order i,f,g,o; activation=relu). Writes duplicated [h|h] and/or flat h.
// ---------------------------------------------------------------------------
__global__ void lstm_gate(const float* __restrict__ P, int KS,
                          const float* __restrict__ c_prev, float* __restrict__ c_out,
                          const float* __restrict__ bias,
                          float* __restrict__ hdup, float* __restrict__ hflat) {
    int idx = blockIdx.x * blockDim.x + threadIdx.x;
    if (idx >= Bn * Hn) return;
    int b = idx / Hn;
    int j = idx - b * Hn;
    float zi = bias[j], zf = bias[Hn + j], zg = bias[2 * Hn + j], zo = bias[3 * Hn + j];
    for (int ks = 0; ks < KS; ks++) {
        const float* zr = P + ((size_t)ks * Bn + b) * NG;
        zi += zr[j]; zf += zr[Hn + j]; zg += zr[2 * Hn + j]; zo += zr[3 * Hn + j];
    }
    float ig = 1.f / (1.f + expf(-zi));
    float fg = 1.f / (1.f + expf(-zf));
    float gg = fmaxf(zg, 0.f);
    float og = 1.f / (1.f + expf(-zo));
    float cn = fg * c_prev[idx] + ig * gg;
    c_out[idx] = cn;
    float h = og * fmaxf(cn, 0.f);
    if (hdup) {
        hdup[(size_t)b * 2 * Hn + j] = h;
        hdup[(size_t)b * 2 * Hn + Hn + j] = h;
    }
    if (hflat) hflat[idx] = h;
}

// ---------------------------------------------------------------------------
// SMEM-staged softmax on (Bn x Vn): one global read + one global write.
// ---------------------------------------------------------------------------
__global__ __launch_bounds__(512)
void softmax_smem(float* __restrict__ probs, const float* __restrict__ bd) {
    extern __shared__ float sx[];
    const int b = blockIdx.x;
    float* row = probs + (size_t)b * Vn;
    const int tid = threadIdx.x;
    const int nt = 512;
    __shared__ float sred[33];

    float m = -3.4e38f;
    for (int i = tid; i < Vn; i += nt) {
        float v = row[i] + bd[i];
        sx[i] = v;
        m = fmaxf(m, v);
    }
#pragma unroll
    for (int o = 16; o > 0; o >>= 1) m = fmaxf(m, __shfl_xor_sync(0xffffffffu, m, o));
    if ((tid & 31) == 0) sred[tid >> 5] = m;
    __syncthreads();
    if (tid == 0) {
        float v = sred[0];
        for (int w = 1; w < nt / 32; w++) v = fmaxf(v, sred[w]);
        sred[32] = v;
    }
    __syncthreads();
    m = sred[32];

    float s = 0.f;
    for (int i = tid; i < Vn; i += nt) {
        float e = expf(sx[i] - m);
        sx[i] = e;
        s += e;
    }
    __syncthreads();
#pragma unroll
    for (int o = 16; o > 0; o >>= 1) s += __shfl_xor_sync(0xffffffffu, s, o);
    if ((tid & 31) == 0) sred[tid >> 5] = s;
    __syncthreads();
    if (tid == 0) {
        float v = 0.f;
        for (int w = 0; w < nt / 32; w++) v += sred[w];
        sred[32] = v;
    }
    __syncthreads();
    float inv = 1.f / sred[32];

    for (int i = tid; i < Vn; i += nt) row[i] = sx[i] * inv;
}

__global__ void copy_tail(const float* __restrict__ h4, const float* __restrict__ c4,
                          float* __restrict__ out) {
    int i = blockIdx.x * blockDim.x + threadIdx.x;
    if (i >= Bn * Hn) return;
    out[(size_t)Bn * Vn + i] = h4[i];
    out[(size_t)Bn * Vn + (size_t)Bn * Hn + i] = c4[i];
}

// ---------------------------------------------------------------------------
// Launch
// ---------------------------------------------------------------------------
extern "C" void kernel_launch(void* const* d_in, const int* in_sizes, int n_in,
                              void* d_out, int out_size) {
    const float* enc = (const float*)d_in[0];
    const float* we  = (const float*)d_in[1];
    const float* h0  = (const float*)d_in[2];
    const float* c0  = (const float*)d_in[3];
    const int*   spk = (const int*)d_in[4];
    // d_in[5] = addressee (unused)
    const float* pe  = (const float*)d_in[6];
    const float* W1 = (const float*)d_in[7];
    const float* U1 = (const float*)d_in[8];
    const float* b1 = (const float*)d_in[9];
    const float* W2 = (const float*)d_in[10];
    const float* U2 = (const float*)d_in[11];
    const float* b2 = (const float*)d_in[12];
    const float* W3 = (const float*)d_in[13];
    const float* U3 = (const float*)d_in[14];
    const float* b3 = (const float*)d_in[15];
    const float* W4 = (const float*)d_in[16];
    const float* U4 = (const float*)d_in[17];
    const float* b4 = (const float*)d_in[18];
    const float* Wd = (const float*)d_in[19];
    const float* bd = (const float*)d_in[20];
    float* out = (float*)d_out;

    float *xp, *pp, *hd, *h4, *cp;
    cudaGetSymbolAddress((void**)&xp, g_x);
    cudaGetSymbolAddress((void**)&pp, g_part);
    cudaGetSymbolAddress((void**)&hd, g_hdup);
    cudaGetSymbolAddress((void**)&h4, g_h4);
    cudaGetSymbolAddress((void**)&cp, g_c);

    cudaFuncSetAttribute(gemm_tall16<0>, cudaFuncAttributeMaxDynamicSharedMemorySize,
                         TALL_SMEM);
    cudaFuncSetAttribute(gemm_tall16<1>, cudaFuncAttributeMaxDynamicSharedMemorySize,
                         TALL_SMEM);
    cudaFuncSetAttribute(softmax_smem, cudaFuncAttributeMaxDynamicSharedMemorySize,
                         Vn * (int)sizeof(float));

    // 1. Build concatenated input
    build_x<<<(Bn * K1 + 255) / 256, 256>>>(enc, we, h0, spk, pe);

    // 2. Layer 1 (TALL): z = [x|h0] @ [W1;U1]  (K=11776, split 11264, KS=8)
    gemm_tall16<1><<<dim3(NG / 64, 1, 8), 256, TALL_SMEM>>>(
        xp, W1, U1, pp, NG, K1, DIN1, K1 / 8);
    lstm_gate<<<(Bn * Hn + 255) / 256, 256>>>(pp, 8, c0, cp, b1, hd, nullptr);

    // 3. Layers 2-4 (WIDE): z = [h|h] @ [W;U]  (K=1024, split 512, KS=4)
    gemm_fp16s<1><<<dim3(NG / 64, Bn / 128, 4), 256>>>(
        hd, W2, U2, pp, Bn, NG, 2 * Hn, Hn, 2 * Hn / 4);
    lstm_gate<<<(Bn * Hn + 255) / 256, 256>>>(pp, 4, cp, cp, b2, hd, nullptr);

    gemm_fp16s<1><<<dim3(NG / 64, Bn / 128, 4), 256>>>(
        hd, W3, U3, pp, Bn, NG, 2 * Hn, Hn, 2 * Hn / 4);
    lstm_gate<<<(Bn * Hn + 255) / 256, 256>>>(pp, 4, cp, cp, b3, hd, nullptr);

    gemm_fp16s<1><<<dim3(NG / 64, Bn / 128, 4), 256>>>(
        hd, W4, U4, pp, Bn, NG, 2 * Hn, Hn, 2 * Hn / 4);
    lstm_gate<<<(Bn * Hn + 255) / 256, 256>>>(pp, 4, cp, cp, b4, nullptr, h4);

    // 4. Decode (TALL): logits = h4 @ Wd (KS=1, direct into out)
    gemm_tall16<0><<<dim3(Vn / 64, 1, 1), 256, TALL_SMEM>>>(
        h4, Wd, nullptr, out, Vn, Hn, 0, Hn);
    softmax_smem<<<Bn, 512, Vn * sizeof(float)>>>(out, bd);

    // 5. Append h4, c4
    if (out_size >= Bn * Vn + 2 * Bn * Hn) {
        copy_tail<<<(Bn * Hn + 255) / 256, 256>>>(h4, cp, out);
    }
}

// round 9
// speedup vs baseline: 2.3372x; 1.0989x over previous
#include <cuda_runtime.h>
#include <cuda_fp16.h>
#include <mma.h>
#include <math.h>
#include <cstdint>

using namespace nvcuda;

// Problem dims
static constexpr int Bn = 256, Sn = 20, En = 512, Hn = 512, Vn = 32000;
static constexpr int DIN1 = Sn * En + 2 * En;   // 11264
static constexpr int K1   = DIN1 + Hn;          // 11776 ([x | h0] concat)
static constexpr int NG   = 4 * Hn;             // 2048 gates

// Scratch (device globals; allocation is forbidden)
__device__ __align__(16) __half g_xh[Bn * K1];       // A of layer 1 (half)
__device__ __align__(16) __half g_hduph[Bn * 2 * Hn]; // [h|h] half (layers 2-4 A)
__device__ __align__(16) __half g_h4h[Bn * Hn];       // h4 half (decode A)
__device__ float g_part[8 * Bn * NG];                 // split-K partials
__device__ float g_h4f[Bn * Hn];                      // h4 f32 (output tail)
__device__ float g_c[Bn * Hn];

// ---------------------------------------------------------------------------
// Helpers
// ---------------------------------------------------------------------------
#define CP16(dst, src) \
    asm volatile("cp.async.cg.shared.global [%0], [%1], 16;\n" :: "r"(dst), "l"(src))

__device__ __forceinline__ void split4h(const float4 f, __half* hi, __half* lo) {
    float v[4] = {f.x, f.y, f.z, f.w};
#pragma unroll
    for (int i = 0; i < 4; i++) {
        __half h = __float2half_rn(v[i]);
        hi[i] = h;
        lo[i] = __float2half_rn(v[i] - __half2float(h));
    }
}

// ---------------------------------------------------------------------------
// build_x: concatenated input row as HALF: [enc | we | pe[spk] | h0]
// ---------------------------------------------------------------------------
__global__ void build_x(const float* __restrict__ enc, const float* __restrict__ we,
                        const float* __restrict__ h0, const int* __restrict__ spk,
                        const float* __restrict__ pe) {
    int idx = blockIdx.x * blockDim.x + threadIdx.x;
    if (idx >= Bn * K1) return;
    int b = idx / K1;
    int k = idx - b * K1;
    float v;
    if (k < Sn * En)            v = enc[b * Sn * En + k];
    else if (k < Sn * En + En)  v = we[b * En + (k - Sn * En)];
    else if (k < DIN1)          v = pe[spk[b] * En + (k - Sn * En - En)];
    else                        v = h0[b * Hn + (k - DIN1)];
    g_xh[idx] = __float2half_rn(v);
}

// ---------------------------------------------------------------------------
// Deep-pipelined fp16 GEMM (tall 256x64, BK=32, 3-stage cp.async).
//   A: half in gmem (pre-rounded activation) -> cp.async direct.
//   B: f32 weights -> cp.async f32 stage -> smem split into bh + bl halves.
//   acc += a*bh; acc += a*bl  (fp32 accumulators, 2-MMA compensation).
// C_partial = A(256xK) @ B(KxN) into Cout + ks*256*N.
// DUAL=1: B row gk < Ksplit from B0 else B1[gk-Ksplit].
// grid = (N/64, 1, KS). 256 threads, 8 warps (4x2), warp tile 64x32.
// ---------------------------------------------------------------------------
static constexpr int ALD = 40;                  // halfs per A row (32+8 pad)
static constexpr int BLD = 72;                  // halfs per B half-plane row
static constexpr int BFLD = 68;                 // floats per B f32 stage row
static constexpr int A_STAGE = 256 * ALD * 2;   // 20480 B
static constexpr int BF_STAGE = 32 * BFLD * 4;  // 8704 B
static constexpr int BH_STAGE = 32 * BLD * 2;   // 4608 B
static constexpr int SA  = 0;                   // 3 stages
static constexpr int SBF = SA + 3 * A_STAGE;    // 3 stages
static constexpr int SBH = SBF + 3 * BF_STAGE;  // 2 buffers
static constexpr int SBL = SBH + 2 * BH_STAGE;  // 2 buffers
static constexpr int GEMM_SMEM = SBL + 2 * BH_STAGE;  // 105984 B

template <int DUAL>
__global__ __launch_bounds__(256, 2)
void gemm_cp(const __half* __restrict__ A, const float* __restrict__ B0,
             const float* __restrict__ B1, float* __restrict__ Cout,
             int N, int K, int Ksplit, int Kchunk) {
    extern __shared__ char smem[];
    uint32_t sb;
    asm("{ .reg .u64 t; cvta.to.shared.u64 t, %1; cvt.u32.u64 %0, t; }"
        : "=r"(sb) : "l"(smem));

    const int n0 = blockIdx.x * 64;
    const int ks = blockIdx.z;
    const int kbase = ks * Kchunk;
    const int iters = Kchunk / 32;
    const int tid = threadIdx.x;

    // A loader: 4 threads per row (4x16B = 64B row), 4 passes of 64 rows
    const int a_row4 = tid >> 2;
    const int a_chk = tid & 3;
    // B loader: 16 threads per row (16x16B = 256B row), 2 passes of 16 rows
    const int b_row16 = tid >> 4;
    const int b_chk = tid & 15;
    // B converter: 8 threads per row (8 floats each)
    const int c_row = tid >> 3;
    const int c_col = (tid & 7) * 8;

    const int wid = tid >> 5;
    const int wm = wid >> 1;   // 0..3 -> m offset wm*64
    const int wn = wid & 1;    // 0..1 -> n offset wn*32

    wmma::fragment<wmma::accumulator, 16, 16, 16, float> acc[4][2];
#pragma unroll
    for (int i = 0; i < 4; i++)
#pragma unroll
        for (int j = 0; j < 2; j++) wmma::fill_fragment(acc[i][j], 0.f);

    auto issue_chunk = [&](int chunk) {
        const int s = chunk % 3;
        const int k0 = kbase + chunk * 32;
        uint32_t sa = sb + SA + s * A_STAGE;
#pragma unroll
        for (int p = 0; p < 4; p++) {
            int row = a_row4 + p * 64;
            const __half* src = A + (size_t)row * K + k0 + a_chk * 8;
            CP16(sa + row * 80 + a_chk * 16, src);
        }
        uint32_t sf = sb + SBF + s * BF_STAGE;
#pragma unroll
        for (int p = 0; p < 2; p++) {
            int gk = k0 + b_row16 + p * 16;
            const float* src;
            if (DUAL && gk >= Ksplit)
                src = B1 + (size_t)(gk - Ksplit) * N + n0 + b_chk * 4;
            else
                src = B0 + (size_t)gk * N + n0 + b_chk * 4;
            CP16(sf + (b_row16 + p * 16) * 272 + b_chk * 16, src);
        }
        asm volatile("cp.async.commit_group;\n");
    };

    issue_chunk(0);
    if (iters > 1) issue_chunk(1);

    for (int it = 0; it < iters; ++it) {
        const int s = it % 3;
        const int sd = it & 1;

        if (it == iters - 1)
            asm volatile("cp.async.wait_group 0;\n");
        else
            asm volatile("cp.async.wait_group 1;\n");
        __syncthreads();   // chunk `it` visible; all warps done with chunk it-1

        if (it + 2 < iters) issue_chunk(it + 2);

        // Convert B f32 stage -> bh/bl half planes (double-buffered)
        {
            const float* bf = (const float*)(smem + SBF + s * BF_STAGE);
            float4 f0 = *(const float4*)(bf + c_row * BFLD + c_col);
            float4 f1 = *(const float4*)(bf + c_row * BFLD + c_col + 4);
            __half h0[4], l0[4], h1[4], l1[4];
            split4h(f0, h0, l0);
            split4h(f1, h1, l1);
            __half* bh = (__half*)(smem + SBH + sd * BH_STAGE);
            __half* bl = (__half*)(smem + SBL + sd * BH_STAGE);
            *(uint2*)&bh[c_row * BLD + c_col] = *(uint2*)h0;
            *(uint2*)&bh[c_row * BLD + c_col + 4] = *(uint2*)h1;
            *(uint2*)&bl[c_row * BLD + c_col] = *(uint2*)l0;
            *(uint2*)&bl[c_row * BLD + c_col + 4] = *(uint2*)l1;
        }
        __syncthreads();

        const __half* ah = (const __half*)(smem + SA + s * A_STAGE) + (wm * 64) * ALD;
        const __half* bh = (const __half*)(smem + SBH + sd * BH_STAGE) + wn * 32;
        const __half* bl = (const __half*)(smem + SBL + sd * BH_STAGE) + wn * 32;

#pragma unroll
        for (int kk = 0; kk < 2; ++kk) {
            wmma::fragment<wmma::matrix_a, 16, 16, 16, __half, wmma::row_major> af[4];
            wmma::fragment<wmma::matrix_b, 16, 16, 16, __half, wmma::row_major> bfh[2],
                bfl[2];
#pragma unroll
            for (int i = 0; i < 4; i++)
                wmma::load_matrix_sync(af[i], ah + i * 16 * ALD + kk * 16, ALD);
#pragma unroll
            for (int j = 0; j < 2; j++) {
                wmma::load_matrix_sync(bfh[j], bh + kk * 16 * BLD + j * 16, BLD);
                wmma::load_matrix_sync(bfl[j], bl + kk * 16 * BLD + j * 16, BLD);
            }
#pragma unroll
            for (int i = 0; i < 4; i++)
#pragma unroll
                for (int j = 0; j < 2; j++) {
                    wmma::mma_sync(acc[i][j], af[i], bfh[j], acc[i][j]);
                    wmma::mma_sync(acc[i][j], af[i], bfl[j], acc[i][j]);
                }
        }
    }

    float* C = Cout + (size_t)ks * 256 * N;
#pragma unroll
    for (int i = 0; i < 4; i++)
#pragma unroll
        for (int j = 0; j < 2; j++)
            wmma::store_matrix_sync(
                C + (size_t)(wm * 64 + i * 16) * N + n0 + wn * 32 + j * 16,
                acc[i][j], N, wmma::mem_row_major);
}

// ---------------------------------------------------------------------------
// Gate kernel: reduce KS split-K partials + bias, LSTM nonlinearity (i,f,g,o;
// activation=relu). Emits half hdup [h|h] and/or half hflat + f32 hflat.
// ---------------------------------------------------------------------------
__global__ void lstm_gate(const float* __restrict__ P, int KS,
                          const float* __restrict__ c_prev, float* __restrict__ c_out,
                          const float* __restrict__ bias,
                          __half* __restrict__ hdup, __half* __restrict__ hflat_h,
                          float* __restrict__ hflat_f) {
    int idx = blockIdx.x * blockDim.x + threadIdx.x;
    if (idx >= Bn * Hn) return;
    int b = idx / Hn;
    int j = idx - b * Hn;
    float zi = bias[j], zf = bias[Hn + j], zg = bias[2 * Hn + j], zo = bias[3 * Hn + j];
    for (int ks = 0; ks < KS; ks++) {
        const float* zr = P + ((size_t)ks * Bn + b) * NG;
        zi += zr[j]; zf += zr[Hn + j]; zg += zr[2 * Hn + j]; zo += zr[3 * Hn + j];
    }
    float ig = 1.f / (1.f + expf(-zi));
    float fg = 1.f / (1.f + expf(-zf));
    float gg = fmaxf(zg, 0.f);
    float og = 1.f / (1.f + expf(-zo));
    float cn = fg * c_prev[idx] + ig * gg;
    c_out[idx] = cn;
    float h = og * fmaxf(cn, 0.f);
    if (hdup) {
        __half hh = __float2half_rn(h);
        hdup[(size_t)b * 2 * Hn + j] = hh;
        hdup[(size_t)b * 2 * Hn + Hn + j] = hh;
    }
    if (hflat_h) hflat_h[idx] = __float2half_rn(h);
    if (hflat_f) hflat_f[idx] = h;
}

// ---------------------------------------------------------------------------
// SMEM-staged softmax on (Bn x Vn): one global read + one global write.
// ---------------------------------------------------------------------------
__global__ __launch_bounds__(512)
void softmax_smem(float* __restrict__ probs, const float* __restrict__ bd) {
    extern __shared__ float sx[];
    const int b = blockIdx.x;
    float* row = probs + (size_t)b * Vn;
    const int tid = threadIdx.x;
    const int nt = 512;
    __shared__ float sred[33];

    float m = -3.4e38f;
    for (int i = tid; i < Vn; i += nt) {
        float v = row[i] + bd[i];
        sx[i] = v;
        m = fmaxf(m, v);
    }
#pragma unroll
    for (int o = 16; o > 0; o >>= 1) m = fmaxf(m, __shfl_xor_sync(0xffffffffu, m, o));
    if ((tid & 31) == 0) sred[tid >> 5] = m;
    __syncthreads();
    if (tid == 0) {
        float v = sred[0];
        for (int w = 1; w < nt / 32; w++) v = fmaxf(v, sred[w]);
        sred[32] = v;
    }
    __syncthreads();
    m = sred[32];

    float s = 0.f;
    for (int i = tid; i < Vn; i += nt) {
        float e = expf(sx[i] - m);
        sx[i] = e;
        s += e;
    }
    __syncthreads();
#pragma unroll
    for (int o = 16; o > 0; o >>= 1) s += __shfl_xor_sync(0xffffffffu, s, o);
    if ((tid & 31) == 0) sred[tid >> 5] = s;
    __syncthreads();
    if (tid == 0) {
        float v = 0.f;
        for (int w = 0; w < nt / 32; w++) v += sred[w];
        sred[32] = v;
    }
    __syncthreads();
    float inv = 1.f / sred[32];

    for (int i = tid; i < Vn; i += nt) row[i] = sx[i] * inv;
}

__global__ void copy_tail(const float* __restrict__ h4, const float* __restrict__ c4,
                          float* __restrict__ out) {
    int i = blockIdx.x * blockDim.x + threadIdx.x;
    if (i >= Bn * Hn) return;
    out[(size_t)Bn * Vn + i] = h4[i];
    out[(size_t)Bn * Vn + (size_t)Bn * Hn + i] = c4[i];
}

// ---------------------------------------------------------------------------
// Launch
// ---------------------------------------------------------------------------
extern "C" void kernel_launch(void* const* d_in, const int* in_sizes, int n_in,
                              void* d_out, int out_size) {
    const float* enc = (const float*)d_in[0];
    const float* we  = (const float*)d_in[1];
    const float* h0  = (const float*)d_in[2];
    const float* c0  = (const float*)d_in[3];
    const int*   spk = (const int*)d_in[4];
    // d_in[5] = addressee (unused)
    const float* pe  = (const float*)d_in[6];
    const float* W1 = (const float*)d_in[7];
    const float* U1 = (const float*)d_in[8];
    const float* b1 = (const float*)d_in[9];
    const float* W2 = (const float*)d_in[10];
    const float* U2 = (const float*)d_in[11];
    const float* b2 = (const float*)d_in[12];
    const float* W3 = (const float*)d_in[13];
    const float* U3 = (const float*)d_in[14];
    const float* b3 = (const float*)d_in[15];
    const float* W4 = (const float*)d_in[16];
    const float* U4 = (const float*)d_in[17];
    const float* b4 = (const float*)d_in[18];
    const float* Wd = (const float*)d_in[19];
    const float* bd = (const float*)d_in[20];
    float* out = (float*)d_out;

    __half *xh, *hdh, *h4h;
    float *pp, *h4f, *cp;
    cudaGetSymbolAddress((void**)&xh, g_xh);
    cudaGetSymbolAddress((void**)&hdh, g_hduph);
    cudaGetSymbolAddress((void**)&h4h, g_h4h);
    cudaGetSymbolAddress((void**)&pp, g_part);
    cudaGetSymbolAddress((void**)&h4f, g_h4f);
    cudaGetSymbolAddress((void**)&cp, g_c);

    cudaFuncSetAttribute(gemm_cp<0>, cudaFuncAttributeMaxDynamicSharedMemorySize,
                         GEMM_SMEM);
    cudaFuncSetAttribute(gemm_cp<1>, cudaFuncAttributeMaxDynamicSharedMemorySize,
                         GEMM_SMEM);
    cudaFuncSetAttribute(softmax_smem, cudaFuncAttributeMaxDynamicSharedMemorySize,
                         Vn * (int)sizeof(float));

    // 1. Build concatenated input (half)
    build_x<<<(Bn * K1 + 255) / 256, 256>>>(enc, we, h0, spk, pe);

    // 2. Layer 1: z = [x|h0] @ [W1;U1]  (K=11776, split 11264, KS=8)
    gemm_cp<1><<<dim3(NG / 64, 1, 8), 256, GEMM_SMEM>>>(
        xh, W1, U1, pp, NG, K1, DIN1, K1 / 8);
    lstm_gate<<<(Bn * Hn + 255) / 256, 256>>>(pp, 8, c0, cp, b1, hdh, nullptr, nullptr);

    // 3. Layers 2-4: z = [h|h] @ [W;U]  (K=1024, split 512, KS=8, iters=4)
    gemm_cp<1><<<dim3(NG / 64, 1, 8), 256, GEMM_SMEM>>>(
        hdh, W2, U2, pp, NG, 2 * Hn, Hn, 2 * Hn / 8);
    lstm_gate<<<(Bn * Hn + 255) / 256, 256>>>(pp, 8, cp, cp, b2, hdh, nullptr, nullptr);

    gemm_cp<1><<<dim3(NG / 64, 1, 8), 256, GEMM_SMEM>>>(
        hdh, W3, U3, pp, NG, 2 * Hn, Hn, 2 * Hn / 8);
    lstm_gate<<<(Bn * Hn + 255) / 256, 256>>>(pp, 8, cp, cp, b3, hdh, nullptr, nullptr);

    gemm_cp<1><<<dim3(NG / 64, 1, 8), 256, GEMM_SMEM>>>(
        hdh, W4, U4, pp, NG, 2 * Hn, Hn, 2 * Hn / 8);
    lstm_gate<<<(Bn * Hn + 255) / 256, 256>>>(pp, 8, cp, cp, b4, nullptr, h4h, h4f);

    // 4. Decode: logits = h4 @ Wd (KS=1, direct into out)
    gemm_cp<0><<<dim3(Vn / 64, 1, 1), 256, GEMM_SMEM>>>(
        h4h, Wd, nullptr, out, Vn, Hn, 0, Hn);
    softmax_smem<<<Bn, 512, Vn * sizeof(float)>>>(out, bd);

    // 5. Append h4, c4 (f32 path)
    if (out_size >= Bn * Vn + 2 * Bn * Hn) {
        copy_tail<<<(Bn * Hn + 255) / 256, 256>>>(h4f, cp, out);
    }
}